// round 6
// baseline (speedup 1.0000x reference)
#include <cuda_runtime.h>
#include <cuda_fp16.h>

#define NN 50000
#define NE 800000
#define ETOT (NE + NN)
#define HD 64
#define HCC 256
#define NT 200000
#define NEG_SLOPE 0.2f

// ---------------- scratch (static device globals; no allocations) ----------------
__device__ __half2 g_hh[(size_t)NN * 128];   // transformed features fp16 [N, 256] as half2
__device__ float g_feat[(size_t)NN * HD];    // per-layer node output (pre-norm) [N, 64]
__device__ float g_ssrcA[NN * 4], g_sdstA[NN * 4];
__device__ float g_ssrcB[NN * 4], g_sdstB[NN * 4];
__device__ int   g_deg[NN];
__device__ int   g_off[NN + 1];
__device__ int   g_pos[NN];
__device__ int   g_csr[ETOT];
__device__ float g_cs1a[HD], g_cs2a[HD], g_cs1b[HD], g_cs2b[HD];

// ---------------- helpers ----------------
__device__ __forceinline__ float warpSum(float v) {
#pragma unroll
    for (int o = 16; o; o >>= 1) v += __shfl_xor_sync(0xffffffffu, v, o);
    return v;
}
__device__ __forceinline__ unsigned f2tf(float f) {
    unsigned r;
    asm("cvt.rna.tf32.f32 %0, %1;" : "=r"(r) : "f"(f));
    return r;
}
__device__ __forceinline__ void mma_tf32(float* d, const unsigned* a, const unsigned* b) {
    asm volatile(
        "mma.sync.aligned.m16n8k8.row.col.f32.tf32.tf32.f32 "
        "{%0,%1,%2,%3}, {%4,%5,%6,%7}, {%8,%9}, {%0,%1,%2,%3};"
        : "+f"(d[0]), "+f"(d[1]), "+f"(d[2]), "+f"(d[3])
        : "r"(a[0]), "r"(a[1]), "r"(a[2]), "r"(a[3]), "r"(b[0]), "r"(b[1]));
}

// ---------------- zero all accumulators ----------------
__global__ void k_zero() {
    int i = blockIdx.x * blockDim.x + threadIdx.x;
    if (i < NN) g_deg[i] = 0;
    if (i < NN * 4) {
        g_ssrcA[i] = 0.f; g_sdstA[i] = 0.f;
        g_ssrcB[i] = 0.f; g_sdstB[i] = 0.f;
    }
    if (i < HD) {
        g_cs1a[i] = 0.f; g_cs2a[i] = 0.f;
        g_cs1b[i] = 0.f; g_cs2b[i] = 0.f;
    }
}

// ---------------- CSR build ----------------
__global__ void k_hist(const int* __restrict__ ei) {
    int i = blockIdx.x * blockDim.x + threadIdx.x;
    if (i >= ETOT) return;
    int dst = (i < NE) ? __ldg(&ei[NE + i]) : (i - NE);
    atomicAdd(&g_deg[dst], 1);
}

__global__ void k_scan() {
    __shared__ int sm[1024];
    int t = threadIdx.x;
    const int per = (NN + 1023) / 1024;
    int base = t * per;
    int s = 0;
    for (int j = 0; j < per; j++) {
        int idx = base + j;
        if (idx < NN) s += g_deg[idx];
    }
    sm[t] = s;
    __syncthreads();
    for (int off = 1; off < 1024; off <<= 1) {
        int v = (t >= off) ? sm[t - off] : 0;
        __syncthreads();
        sm[t] += v;
        __syncthreads();
    }
    int run = sm[t] - s;  // exclusive prefix
    for (int j = 0; j < per; j++) {
        int idx = base + j;
        if (idx < NN) {
            g_off[idx] = run;
            g_pos[idx] = run;
            run += g_deg[idx];
        }
    }
    if (t == 0) g_off[NN] = ETOT;
}

__global__ void k_scatter(const int* __restrict__ ei) {
    int i = blockIdx.x * blockDim.x + threadIdx.x;
    if (i >= ETOT) return;
    int src, dst;
    if (i < NE) { src = __ldg(&ei[i]); dst = __ldg(&ei[NE + i]); }
    else        { src = i - NE; dst = src; }
    int p = atomicAdd(&g_pos[dst], 1);
    g_csr[p] = src;
}

// ---------------- tf32 GEMM + fused norm-on-load + fp16 store + fused scores ----------------
// layer==0: A = param (x), no input norm, scores -> A arrays
// layer==1: A = g_feat with graphnorm(stats a)+relu applied on load, scores -> B arrays
__global__ void __launch_bounds__(256) k_gemm(const float* __restrict__ A,
                                              const float* __restrict__ B,
                                              int M, int K, int layer,
                                              const float* __restrict__ av_src,
                                              const float* __restrict__ av_dst,
                                              const float* __restrict__ nw,
                                              const float* __restrict__ nb,
                                              const float* __restrict__ ns) {
    __shared__ unsigned As[2][16][136];
    __shared__ unsigned Bs[2][16][136];
    __shared__ float nsc[64], nsh[64];

    int tid = threadIdx.x;
    if (layer && tid < 64) {
        float mu = g_cs1a[tid] * (1.f / NN);
        float m2 = g_cs2a[tid] * (1.f / NN);
        float tt = mu * __ldg(&ns[tid]);
        float var = m2 - 2.f * tt * mu + tt * tt;
        float rs = rsqrtf(var + 1e-5f);
        float sc = __ldg(&nw[tid]) * rs;
        nsc[tid] = sc;
        nsh[tid] = __ldg(&nb[tid]) - tt * sc;
    }
    __syncthreads();

    const float* Ap = layer ? g_feat : A;

    int lane = tid & 31;
    int wid = tid >> 5;
    int warp_m = wid >> 2;   // 0..1
    int warp_n = wid & 3;    // 0..3
    int gid = lane >> 2;     // 0..7
    int tig = lane & 3;      // 0..3

    int colBlk = blockIdx.x & 1;
    int rowBlk = blockIdx.x >> 1;
    int row0 = rowBlk * 128;
    int col0 = colBlk * 128;

    int NC = K / 16;
    float acc[4][4][4];
#pragma unroll
    for (int mt = 0; mt < 4; mt++)
#pragma unroll
        for (int nt = 0; nt < 4; nt++)
#pragma unroll
            for (int q = 0; q < 4; q++) acc[mt][nt][q] = 0.f;

    int aRow = tid >> 2;
    int aK4 = (tid & 3) * 4;
    int bK = tid >> 5;
    int bN = lane * 4;

    float4 aReg[2], bReg[2];

    // A-load lambda behavior inline: load + optional norm+relu
    auto loadA = [&](int r, int k) -> float4 {
        if (r >= M) return make_float4(0.f, 0.f, 0.f, 0.f);
        float4 v = __ldg((const float4*)(Ap + (size_t)r * K + k));
        if (layer) {
            v.x = fmaxf(0.f, v.x * nsc[k + 0] + nsh[k + 0]);
            v.y = fmaxf(0.f, v.y * nsc[k + 1] + nsh[k + 1]);
            v.z = fmaxf(0.f, v.z * nsc[k + 2] + nsh[k + 2]);
            v.w = fmaxf(0.f, v.w * nsc[k + 3] + nsh[k + 3]);
        }
        return v;
    };

    {
#pragma unroll
        for (int it = 0; it < 2; it++) {
            aReg[it] = loadA(row0 + aRow + it * 64, aK4);
            bReg[it] = __ldg((const float4*)(B + (size_t)(bK + it * 8) * HCC + col0 + bN));
        }
#pragma unroll
        for (int it = 0; it < 2; it++) {
            int rr = aRow + it * 64;
            As[0][aK4 + 0][rr] = f2tf(aReg[it].x);
            As[0][aK4 + 1][rr] = f2tf(aReg[it].y);
            As[0][aK4 + 2][rr] = f2tf(aReg[it].z);
            As[0][aK4 + 3][rr] = f2tf(aReg[it].w);
            unsigned* bp = &Bs[0][bK + it * 8][bN];
            bp[0] = f2tf(bReg[it].x);
            bp[1] = f2tf(bReg[it].y);
            bp[2] = f2tf(bReg[it].z);
            bp[3] = f2tf(bReg[it].w);
        }
    }
    __syncthreads();

    for (int c = 0; c < NC; c++) {
        int buf = c & 1;
        if (c + 1 < NC) {
            int k0 = (c + 1) * 16;
#pragma unroll
            for (int it = 0; it < 2; it++) {
                aReg[it] = loadA(row0 + aRow + it * 64, k0 + aK4);
                bReg[it] = __ldg((const float4*)(B + (size_t)(k0 + bK + it * 8) * HCC + col0 + bN));
            }
        }
        int mrow = warp_m * 64;
        int ncol = warp_n * 32;
#pragma unroll
        for (int ks = 0; ks < 2; ks++) {
            unsigned af[4][4], bf[4][2];
#pragma unroll
            for (int mt = 0; mt < 4; mt++) {
                int rb = mrow + mt * 16 + gid;
                af[mt][0] = As[buf][ks * 8 + tig][rb];
                af[mt][1] = As[buf][ks * 8 + tig][rb + 8];
                af[mt][2] = As[buf][ks * 8 + tig + 4][rb];
                af[mt][3] = As[buf][ks * 8 + tig + 4][rb + 8];
            }
#pragma unroll
            for (int nt = 0; nt < 4; nt++) {
                int nb2 = ncol + nt * 8 + gid;
                bf[nt][0] = Bs[buf][ks * 8 + tig][nb2];
                bf[nt][1] = Bs[buf][ks * 8 + tig + 4][nb2];
            }
#pragma unroll
            for (int mt = 0; mt < 4; mt++)
#pragma unroll
                for (int nt = 0; nt < 4; nt++)
                    mma_tf32(acc[mt][nt], af[mt], bf[nt]);
        }
        __syncthreads();
        if (c + 1 < NC) {
            int nb = (c + 1) & 1;
#pragma unroll
            for (int it = 0; it < 2; it++) {
                int rr = aRow + it * 64;
                As[nb][aK4 + 0][rr] = f2tf(aReg[it].x);
                As[nb][aK4 + 1][rr] = f2tf(aReg[it].y);
                As[nb][aK4 + 2][rr] = f2tf(aReg[it].z);
                As[nb][aK4 + 3][rr] = f2tf(aReg[it].w);
                unsigned* bp = &Bs[nb][bK + it * 8][bN];
                bp[0] = f2tf(bReg[it].x);
                bp[1] = f2tf(bReg[it].y);
                bp[2] = f2tf(bReg[it].z);
                bp[3] = f2tf(bReg[it].w);
            }
            __syncthreads();
        }
    }

    // ---- epilogue 1: fp16 store of h ----
#pragma unroll
    for (int mt = 0; mt < 4; mt++) {
        int r = row0 + warp_m * 64 + mt * 16 + gid;
#pragma unroll
        for (int nt = 0; nt < 4; nt++) {
            int cc = col0 + warp_n * 32 + nt * 8 + tig * 2;
            if (r < M)
                g_hh[(size_t)r * 128 + cc / 2] = __floats2half2_rn(acc[mt][nt][0], acc[mt][nt][1]);
            if (r + 8 < M)
                g_hh[(size_t)(r + 8) * 128 + cc / 2] = __floats2half2_rn(acc[mt][nt][2], acc[mt][nt][3]);
        }
    }

    // ---- epilogue 2: fused attention scores (fp32 accuracy) ----
    // This warp's 32-col span lies in exactly one head.
    int head = (col0 + warp_n * 32) >> 6;
    float aS[8], aD[8];
#pragma unroll
    for (int nt = 0; nt < 4; nt++) {
        int ch = (col0 + warp_n * 32 + nt * 8 + tig * 2) & 63;
        aS[nt * 2 + 0] = __ldg(&av_src[head * 64 + ch]);
        aS[nt * 2 + 1] = __ldg(&av_src[head * 64 + ch + 1]);
        aD[nt * 2 + 0] = __ldg(&av_dst[head * 64 + ch]);
        aD[nt * 2 + 1] = __ldg(&av_dst[head * 64 + ch + 1]);
    }
    float* ssrc = layer ? g_ssrcB : g_ssrcA;
    float* sdst = layer ? g_sdstB : g_sdstA;
#pragma unroll
    for (int mt = 0; mt < 4; mt++) {
#pragma unroll
        for (int half = 0; half < 2; half++) {
            float ps = 0.f, pd = 0.f;
#pragma unroll
            for (int nt = 0; nt < 4; nt++) {
                float v0 = acc[mt][nt][half * 2 + 0];
                float v1 = acc[mt][nt][half * 2 + 1];
                ps += v0 * aS[nt * 2] + v1 * aS[nt * 2 + 1];
                pd += v0 * aD[nt * 2] + v1 * aD[nt * 2 + 1];
            }
            ps += __shfl_xor_sync(0xffffffffu, ps, 1);
            ps += __shfl_xor_sync(0xffffffffu, ps, 2);
            pd += __shfl_xor_sync(0xffffffffu, pd, 1);
            pd += __shfl_xor_sync(0xffffffffu, pd, 2);
            int r = row0 + warp_m * 64 + mt * 16 + gid + half * 8;
            if (tig == 0 && r < M) {
                atomicAdd(&ssrc[r * 4 + head], ps);
                atomicAdd(&sdst[r * 4 + head], pd);
            }
        }
    }
}

// ---------------- GAT aggregate (fp16 gather) + fused GraphNorm stats ----------------
// Grid: exactly NN/8 blocks of 256 (NN divisible by 8).
__global__ void __launch_bounds__(256) k_aggregate(const float* __restrict__ bias, int layer) {
    __shared__ float4 s_w[8][32];
    __shared__ float s_sum[64], s_sq[64];
    int tid = threadIdx.x;
    if (tid < 64) { s_sum[tid] = 0.f; s_sq[tid] = 0.f; }
    __syncthreads();

    int wid = tid >> 5;
    int lane = tid & 31;
    int w = blockIdx.x * 8 + wid;
    int beg = g_off[w], end = g_off[w + 1];
    int head = lane >> 3;

    const float* ssrc = layer ? g_ssrcB : g_ssrcA;
    const float* sdstp = layer ? g_sdstB : g_sdstA;
    float4 sd = __ldg((const float4*)(sdstp + w * 4));

    float4 acc0 = make_float4(0.f, 0.f, 0.f, 0.f);
    float4 acc1 = make_float4(0.f, 0.f, 0.f, 0.f);
    float4 den = make_float4(0.f, 0.f, 0.f, 0.f);

    for (int base = beg; base < end; base += 32) {
        int n = end - base;
        if (n > 32) n = 32;
        int u = 0;
        float4 w4 = make_float4(0.f, 0.f, 0.f, 0.f);
        if (lane < n) {
            u = __ldg(&g_csr[base + lane]);
            float4 ss = __ldg((const float4*)(ssrc + 4 * u));
            float e0 = ss.x + sd.x; e0 = fmaxf(e0, NEG_SLOPE * e0);
            float e1 = ss.y + sd.y; e1 = fmaxf(e1, NEG_SLOPE * e1);
            float e2 = ss.z + sd.z; e2 = fmaxf(e2, NEG_SLOPE * e2);
            float e3 = ss.w + sd.w; e3 = fmaxf(e3, NEG_SLOPE * e3);
            w4 = make_float4(__expf(e0), __expf(e1), __expf(e2), __expf(e3));
            den.x += w4.x; den.y += w4.y; den.z += w4.z; den.w += w4.w;
        }
        s_w[wid][lane] = w4;
        __syncwarp();
#pragma unroll 4
        for (int j = 0; j < n; j++) {
            int uj = __shfl_sync(0xffffffffu, u, j);
            float wk = ((const float*)&s_w[wid][j])[head];
            uint4 pk = __ldg((const uint4*)(g_hh + (size_t)uj * 128 + lane * 4));
            float2 f0 = __half22float2(*(__half2*)&pk.x);
            float2 f1 = __half22float2(*(__half2*)&pk.y);
            float2 f2 = __half22float2(*(__half2*)&pk.z);
            float2 f3 = __half22float2(*(__half2*)&pk.w);
            acc0.x += wk * f0.x; acc0.y += wk * f0.y; acc0.z += wk * f1.x; acc0.w += wk * f1.y;
            acc1.x += wk * f2.x; acc1.y += wk * f2.y; acc1.z += wk * f3.x; acc1.w += wk * f3.y;
        }
        __syncwarp();
    }

    den.x = warpSum(den.x);
    den.y = warpSum(den.y);
    den.z = warpSum(den.z);
    den.w = warpSum(den.w);
    float dh = head == 0 ? den.x : head == 1 ? den.y : head == 2 ? den.z : den.w;
    float inv = 1.0f / (dh + 1e-16f);
    acc0.x *= inv; acc0.y *= inv; acc0.z *= inv; acc0.w *= inv;
    acc1.x *= inv; acc1.y *= inv; acc1.z *= inv; acc1.w *= inv;

#pragma unroll
    for (int o = 8; o < 32; o <<= 1) {
        acc0.x += __shfl_xor_sync(0xffffffffu, acc0.x, o);
        acc0.y += __shfl_xor_sync(0xffffffffu, acc0.y, o);
        acc0.z += __shfl_xor_sync(0xffffffffu, acc0.z, o);
        acc0.w += __shfl_xor_sync(0xffffffffu, acc0.w, o);
        acc1.x += __shfl_xor_sync(0xffffffffu, acc1.x, o);
        acc1.y += __shfl_xor_sync(0xffffffffu, acc1.y, o);
        acc1.z += __shfl_xor_sync(0xffffffffu, acc1.z, o);
        acc1.w += __shfl_xor_sync(0xffffffffu, acc1.w, o);
    }
    if (lane < 8) {
        const float4* bp = (const float4*)(bias + lane * 8);
        float4 b0 = __ldg(bp), b1 = __ldg(bp + 1);
        float ov[8];
        ov[0] = acc0.x * 0.25f + b0.x; ov[1] = acc0.y * 0.25f + b0.y;
        ov[2] = acc0.z * 0.25f + b0.z; ov[3] = acc0.w * 0.25f + b0.w;
        ov[4] = acc1.x * 0.25f + b1.x; ov[5] = acc1.y * 0.25f + b1.y;
        ov[6] = acc1.z * 0.25f + b1.z; ov[7] = acc1.w * 0.25f + b1.w;
        float4* op = (float4*)(g_feat + (size_t)w * HD + lane * 8);
        op[0] = make_float4(ov[0], ov[1], ov[2], ov[3]);
        op[1] = make_float4(ov[4], ov[5], ov[6], ov[7]);
        int cb = lane * 8;
#pragma unroll
        for (int q = 0; q < 8; q++) {
            atomicAdd(&s_sum[cb + q], ov[q]);
            atomicAdd(&s_sq[cb + q], ov[q] * ov[q]);
        }
    }
    __syncthreads();
    if (tid < 64) {
        atomicAdd(layer ? &g_cs1b[tid] : &g_cs1a[tid], s_sum[tid]);
        atomicAdd(layer ? &g_cs2b[tid] : &g_cs2a[tid], s_sq[tid]);
    }
}

// ---------------- triplet: fused graphnorm(layer2)+relu + layernorm + fc ----------------
__global__ void __launch_bounds__(256) k_triplet(const int* __restrict__ trip,
        const float* __restrict__ g2w, const float* __restrict__ g2b, const float* __restrict__ g2s,
        const float* __restrict__ lnw, const float* __restrict__ lnb,
        const float* __restrict__ fcw, const float* __restrict__ fcb,
        float* __restrict__ out) {
    __shared__ float nsc[64], nsh[64];
    int tid = threadIdx.x;
    if (tid < 64) {
        float mu = g_cs1b[tid] * (1.f / NN);
        float m2 = g_cs2b[tid] * (1.f / NN);
        float tt = mu * __ldg(&g2s[tid]);
        float var = m2 - 2.f * tt * mu + tt * tt;
        float rs = rsqrtf(var + 1e-5f);
        float sc = __ldg(&g2w[tid]) * rs;
        nsc[tid] = sc;
        nsh[tid] = __ldg(&g2b[tid]) - tt * sc;
    }
    __syncthreads();

    int w = blockIdx.x * 8 + (tid >> 5);
    int lane = tid & 31;
    int n0 = __ldg(&trip[w * 4 + 0]);
    int n1 = __ldg(&trip[w * 4 + 1]);
    int n2 = __ldg(&trip[w * 4 + 2]);
    int n3 = __ldg(&trip[w * 4 + 3]);
    float v[8];
#pragma unroll
    for (int k = 0; k < 8; k++) {
        int i = lane + 32 * k;
        int node = (k < 2) ? n0 : (k < 4) ? n1 : (k < 6) ? n2 : n3;
        int ch = i & 63;
        float raw = __ldg(&g_feat[(size_t)node * HD + ch]);
        v[k] = fmaxf(0.f, raw * nsc[ch] + nsh[ch]);
    }
    float s = 0.f;
#pragma unroll
    for (int k = 0; k < 8; k++) s += v[k];
    s = warpSum(s);
    float mean = s * (1.f / 256.f);
    float q = 0.f;
#pragma unroll
    for (int k = 0; k < 8; k++) { float d = v[k] - mean; q += d * d; }
    q = warpSum(q);
    float r = rsqrtf(q * (1.f / 256.f) + 1e-5f);
    float acc = 0.f;
#pragma unroll
    for (int k = 0; k < 8; k++) {
        int i = lane + 32 * k;
        acc += ((v[k] - mean) * r * __ldg(&lnw[i]) + __ldg(&lnb[i])) * __ldg(&fcw[i]);
    }
    acc = warpSum(acc);
    if (lane == 0) out[w] = acc + fcb[0];
}

// ---------------- launch ----------------
extern "C" void kernel_launch(void* const* d_in, const int* in_sizes, int n_in,
                              void* d_out, int out_size) {
    const float* x   = (const float*)d_in[0];
    const float* W1  = (const float*)d_in[2];
    const float* as1 = (const float*)d_in[3];
    const float* ad1 = (const float*)d_in[4];
    const float* b1  = (const float*)d_in[5];
    const float* W2  = (const float*)d_in[6];
    const float* as2 = (const float*)d_in[7];
    const float* ad2 = (const float*)d_in[8];
    const float* b2  = (const float*)d_in[9];
    const float* g1w = (const float*)d_in[10];
    const float* g1b = (const float*)d_in[11];
    const float* g1s = (const float*)d_in[12];
    const float* g2w = (const float*)d_in[13];
    const float* g2b = (const float*)d_in[14];
    const float* g2s = (const float*)d_in[15];
    const float* lnw = (const float*)d_in[16];
    const float* lnb = (const float*)d_in[17];
    const float* fcw = (const float*)d_in[18];
    const float* fcb = (const float*)d_in[19];
    const int*   ei  = (const int*)d_in[20];
    const int*   trp = (const int*)d_in[21];
    float* out = (float*)d_out;

    int gemmGrid = ((NN + 127) / 128) * 2;

    k_zero<<<(NN * 4 + 255) / 256, 256>>>();
    k_hist<<<(ETOT + 255) / 256, 256>>>(ei);
    k_scan<<<1, 1024>>>();
    k_scatter<<<(ETOT + 255) / 256, 256>>>(ei);

    // layer 1: gemm (+fp16 h, +scores), aggregate (+stats)
    k_gemm<<<gemmGrid, 256>>>(x, W1, NN, 128, 0, as1, ad1, nullptr, nullptr, nullptr);
    k_aggregate<<<NN / 8, 256>>>(b1, 0);

    // layer 2: gemm with fused norm+relu on load
    k_gemm<<<gemmGrid, 256>>>(nullptr, W2, NN, 64, 1, as2, ad2, g1w, g1b, g1s);
    k_aggregate<<<NN / 8, 256>>>(b2, 1);

    // head: fused norm+relu + layernorm + fc
    k_triplet<<<NT / 8, 256>>>(trp, g2w, g2b, g2s, lnw, lnb, fcw, fcb, out);
}